// round 1
// baseline (speedup 1.0000x reference)
#include <cuda_runtime.h>
#include <math_constants.h>

// ---------------------------------------------------------------------------
// EwaldReciprocal: B=2, N=4096, NK=4096
//   kc[k]      = 2*pi * kvec[k,:] @ cell_inv           (O(NK))
//   theta      = kc[k] . coords[b,n]
//   S[b,k]     = sum_n q[b,n] * exp(i*theta)           (phase 1)
//   recip[b,n] = sum_k expfac[k]*(Sre*cos + Sim*sin)   (phase 2)
//   phi        = recip * BOHR/(pi*vol) - q * 2*bewald*BOHR/sqrt(pi)
//   out        = [0.5*q*phi (B*N floats), phi (B*N floats)]
// ---------------------------------------------------------------------------

#define MAXK   8192
#define MAXBK  32768
#define MAXBN  32768

__device__ float g_kc[MAXK * 3];
__device__ float g_Sre[MAXBK];
__device__ float g_Sim[MAXBK];
__device__ float g_recip[MAXBN];

// ---------------- kernel 1: kc = 2*pi * kvec @ cell_inv --------------------
__global__ void kc_kernel(const float* __restrict__ kvec,
                          const float* __restrict__ cell_inv, int NK) {
    int k = blockIdx.x * blockDim.x + threadIdx.x;
    if (k >= NK) return;
    const float twopi = 6.283185307179586f;
    float kx = kvec[k * 3 + 0], ky = kvec[k * 3 + 1], kz = kvec[k * 3 + 2];
    // kc[j] = 2pi * sum_d kvec[d] * cell_inv[d][j]   (cell_inv row-major 3x3)
    float c0 = twopi * (kx * cell_inv[0] + ky * cell_inv[3] + kz * cell_inv[6]);
    float c1 = twopi * (kx * cell_inv[1] + ky * cell_inv[4] + kz * cell_inv[7]);
    float c2 = twopi * (kx * cell_inv[2] + ky * cell_inv[5] + kz * cell_inv[8]);
    g_kc[k * 3 + 0] = c0;
    g_kc[k * 3 + 1] = c1;
    g_kc[k * 3 + 2] = c2;
}

// ---------------- kernel 2: zero accumulators -------------------------------
__global__ void zero_kernel(int BK, int BN) {
    int i = blockIdx.x * blockDim.x + threadIdx.x;
    if (i < BK) { g_Sre[i] = 0.0f; g_Sim[i] = 0.0f; }
    if (i < BN) { g_recip[i] = 0.0f; }
}

// ---------------- kernel 3: structure factor --------------------------------
// thread = one k; grid.y = batch; grid.z = atom chunk; shared tile of atoms.
#define SF_BLK 256
__global__ void sf_kernel(const float* __restrict__ coords,
                          const float* __restrict__ q,
                          int N, int NK, int nchunk) {
    __shared__ float4 sh[SF_BLK];
    int k = blockIdx.x * SF_BLK + threadIdx.x;
    int b = blockIdx.y;
    int n0 = blockIdx.z * nchunk;
    int n1 = min(n0 + nchunk, N);

    float kcx = 0.f, kcy = 0.f, kcz = 0.f;
    if (k < NK) {
        kcx = g_kc[k * 3 + 0];
        kcy = g_kc[k * 3 + 1];
        kcz = g_kc[k * 3 + 2];
    }
    float sre = 0.f, sim = 0.f;

    for (int t = n0; t < n1; t += SF_BLK) {
        int nt = min(SF_BLK, n1 - t);
        if ((int)threadIdx.x < nt) {
            int n = t + threadIdx.x;
            const float* cp = coords + ((size_t)b * N + n) * 3;
            sh[threadIdx.x] = make_float4(cp[0], cp[1], cp[2], q[(size_t)b * N + n]);
        }
        __syncthreads();
        #pragma unroll 4
        for (int j = 0; j < nt; j++) {
            float4 a = sh[j];                      // smem broadcast
            float th = fmaf(kcx, a.x, fmaf(kcy, a.y, kcz * a.z));
            float s, c;
            __sincosf(th, &s, &c);
            sre = fmaf(a.w, c, sre);
            sim = fmaf(a.w, s, sim);
        }
        __syncthreads();
    }
    if (k < NK) {
        atomicAdd(&g_Sre[b * NK + k], sre);
        atomicAdd(&g_Sim[b * NK + k], sim);
    }
}

// ---------------- kernel 4: reciprocal-space potential per atom -------------
// thread = one atom; grid.y = batch; grid.z = k chunk; shared tile of k data.
#define RC_BLK 256
__global__ void recip_kernel(const float* __restrict__ coords,
                             const float* __restrict__ expfac,
                             int N, int NK, int kchunk) {
    __shared__ float skx[RC_BLK], sky[RC_BLK], skz[RC_BLK];
    __shared__ float ser[RC_BLK], sei[RC_BLK];
    int n = blockIdx.x * RC_BLK + threadIdx.x;
    int b = blockIdx.y;
    int k0 = blockIdx.z * kchunk;
    int k1 = min(k0 + kchunk, NK);

    float x = 0.f, y = 0.f, z = 0.f;
    if (n < N) {
        const float* cp = coords + ((size_t)b * N + n) * 3;
        x = cp[0]; y = cp[1]; z = cp[2];
    }
    float acc = 0.f;

    for (int t = k0; t < k1; t += RC_BLK) {
        int nt = min(RC_BLK, k1 - t);
        if ((int)threadIdx.x < nt) {
            int k = t + threadIdx.x;
            skx[threadIdx.x] = g_kc[k * 3 + 0];
            sky[threadIdx.x] = g_kc[k * 3 + 1];
            skz[threadIdx.x] = g_kc[k * 3 + 2];
            float e = expfac[k];
            ser[threadIdx.x] = e * g_Sre[b * NK + k];
            sei[threadIdx.x] = e * g_Sim[b * NK + k];
        }
        __syncthreads();
        #pragma unroll 4
        for (int j = 0; j < nt; j++) {
            float th = fmaf(skx[j], x, fmaf(sky[j], y, skz[j] * z));
            float s, c;
            __sincosf(th, &s, &c);
            acc = fmaf(ser[j], c, acc);
            acc = fmaf(sei[j], s, acc);
        }
        __syncthreads();
    }
    if (n < N) atomicAdd(&g_recip[b * N + n], acc);
}

// ---------------- kernel 5: finalize -----------------------------------------
__global__ void fin_kernel(const float* __restrict__ q,
                           const float* __restrict__ volume,
                           const float* __restrict__ bewald,
                           float* __restrict__ out, int BN) {
    int i = blockIdx.x * blockDim.x + threadIdx.x;
    if (i >= BN) return;
    const float BOHR = 1.8897261258369282f;
    const float INV_SQRT_PI = 0.5641895835477563f;
    float scale = BOHR / (CUDART_PI_F * volume[0]);
    float selfc = 2.0f * bewald[0] * BOHR * INV_SQRT_PI;
    float qi = q[i];
    float phi = g_recip[i] * scale - qi * selfc;
    out[i] = 0.5f * qi * phi;
    out[BN + i] = phi;
}

// ---------------------------------------------------------------------------
extern "C" void kernel_launch(void* const* d_in, const int* in_sizes, int n_in,
                              void* d_out, int out_size) {
    const float* coords   = (const float*)d_in[0];
    const float* q        = (const float*)d_in[1];
    const float* cell_inv = (const float*)d_in[2];
    const float* kvec     = (const float*)d_in[3];
    const float* expfac   = (const float*)d_in[4];
    const float* volume   = (const float*)d_in[5];
    const float* bewald   = (const float*)d_in[6];
    float* out = (float*)d_out;

    int BN = in_sizes[1];       // B*N
    int NK = in_sizes[4];       // number of k-vectors
    int B  = 2;                 // fixed for this problem's shapes
    int N  = BN / B;
    int BK = B * NK;

    // 1. kc
    kc_kernel<<<(NK + 255) / 256, 256>>>(kvec, cell_inv, NK);

    // 2. zero accumulators
    int zmax = max(BK, BN);
    zero_kernel<<<(zmax + 255) / 256, 256>>>(BK, BN);

    // 3. structure factors: split atom loop into 8 chunks for occupancy
    {
        int nchunks = 8;
        int nchunk = (N + nchunks - 1) / nchunks;
        dim3 grid((NK + SF_BLK - 1) / SF_BLK, B, nchunks);
        sf_kernel<<<grid, SF_BLK>>>(coords, q, N, NK, nchunk);
    }

    // 4. recip: split k loop into 8 chunks
    {
        int kchunks = 8;
        int kchunk = (NK + kchunks - 1) / kchunks;
        dim3 grid((N + RC_BLK - 1) / RC_BLK, B, kchunks);
        recip_kernel<<<grid, RC_BLK>>>(coords, expfac, N, NK, kchunk);
    }

    // 5. finalize both outputs
    fin_kernel<<<(BN + 255) / 256, 256>>>(q, volume, bewald, out, BN);
}

// round 2
// speedup vs baseline: 1.0892x; 1.0892x over previous
#include <cuda_runtime.h>
#include <math_constants.h>

// ---------------------------------------------------------------------------
// EwaldReciprocal: B=2, N=4096, NK=4096
// Phase 1 (sf):    S[b,k]     = sum_n q[b,n] * exp(i * kc[k].r[b,n])
// Phase 2 (recip): recip[b,n] = sum_k expfac[k]*(Sre*cos(th) + Sim*sin(th))
// MUFU-bound: ~14us/phase chip floor. This version: high occupancy (64 chunks),
// packed smem tiles (float4/float2), 2 thetas per thread for ILP.
// ---------------------------------------------------------------------------

#define MAXK   8192
#define MAXBK  32768
#define MAXBN  32768

__device__ float4 g_kc4[MAXK];      // 2*pi * kvec @ cell_inv  (w unused)
__device__ float  g_Sre[MAXBK];
__device__ float  g_Sim[MAXBK];
__device__ float2 g_es[MAXBK];      // expfac[k] * (Sre, Sim)
__device__ float  g_recip[MAXBN];

// ---------------- kernel 1: kc = 2*pi * kvec @ cell_inv --------------------
__global__ void kc_kernel(const float* __restrict__ kvec,
                          const float* __restrict__ cell_inv, int NK) {
    int k = blockIdx.x * blockDim.x + threadIdx.x;
    if (k >= NK) return;
    const float twopi = 6.283185307179586f;
    float kx = kvec[k * 3 + 0], ky = kvec[k * 3 + 1], kz = kvec[k * 3 + 2];
    float c0 = twopi * (kx * cell_inv[0] + ky * cell_inv[3] + kz * cell_inv[6]);
    float c1 = twopi * (kx * cell_inv[1] + ky * cell_inv[4] + kz * cell_inv[7]);
    float c2 = twopi * (kx * cell_inv[2] + ky * cell_inv[5] + kz * cell_inv[8]);
    g_kc4[k] = make_float4(c0, c1, c2, 0.0f);
}

// ---------------- kernel 2: zero accumulators -------------------------------
__global__ void zero_kernel(int BK, int BN) {
    int i = blockIdx.x * blockDim.x + threadIdx.x;
    if (i < BK) { g_Sre[i] = 0.0f; g_Sim[i] = 0.0f; }
    if (i < BN) { g_recip[i] = 0.0f; }
}

// ---------------- kernel 3: structure factor --------------------------------
// 2 k-vectors per thread (block covers 512 k's); grid.z = atom chunks.
#define SF_BLK 256
__global__ void sf_kernel(const float* __restrict__ coords,
                          const float* __restrict__ q,
                          int N, int NK, int nchunk) {
    __shared__ float4 sh[SF_BLK];
    int b  = blockIdx.y;
    int kA = blockIdx.x * (SF_BLK * 2) + threadIdx.x;
    int kB = kA + SF_BLK;
    int n0 = blockIdx.z * nchunk;
    int n1 = min(n0 + nchunk, N);

    float4 kcA = make_float4(0.f, 0.f, 0.f, 0.f);
    float4 kcB = make_float4(0.f, 0.f, 0.f, 0.f);
    if (kA < NK) kcA = g_kc4[kA];
    if (kB < NK) kcB = g_kc4[kB];

    float sreA = 0.f, simA = 0.f, sreB = 0.f, simB = 0.f;

    for (int t = n0; t < n1; t += SF_BLK) {
        int nt = min(SF_BLK, n1 - t);
        if ((int)threadIdx.x < nt) {
            int n = t + threadIdx.x;
            const float* cp = coords + ((size_t)b * N + n) * 3;
            sh[threadIdx.x] = make_float4(cp[0], cp[1], cp[2], q[(size_t)b * N + n]);
        }
        __syncthreads();
        #pragma unroll 4
        for (int j = 0; j < nt; j++) {
            float4 a = sh[j];
            float thA = fmaf(kcA.x, a.x, fmaf(kcA.y, a.y, kcA.z * a.z));
            float thB = fmaf(kcB.x, a.x, fmaf(kcB.y, a.y, kcB.z * a.z));
            float sA, cA, sB, cB;
            __sincosf(thA, &sA, &cA);
            __sincosf(thB, &sB, &cB);
            sreA = fmaf(a.w, cA, sreA);
            simA = fmaf(a.w, sA, simA);
            sreB = fmaf(a.w, cB, sreB);
            simB = fmaf(a.w, sB, simB);
        }
        __syncthreads();
    }
    if (kA < NK) {
        atomicAdd(&g_Sre[b * NK + kA], sreA);
        atomicAdd(&g_Sim[b * NK + kA], simA);
    }
    if (kB < NK) {
        atomicAdd(&g_Sre[b * NK + kB], sreB);
        atomicAdd(&g_Sim[b * NK + kB], simB);
    }
}

// ---------------- kernel 3.5: fold expfac into S -----------------------------
__global__ void es_kernel(const float* __restrict__ expfac, int NK, int BK) {
    int i = blockIdx.x * blockDim.x + threadIdx.x;
    if (i >= BK) return;
    float e = expfac[i % NK];
    g_es[i] = make_float2(e * g_Sre[i], e * g_Sim[i]);
}

// ---------------- kernel 4: reciprocal-space potential per atom -------------
// 2 atoms per thread (block covers 512 atoms); grid.z = k chunks.
#define RC_BLK 256
__global__ void recip_kernel(const float* __restrict__ coords,
                             int N, int NK, int kchunk) {
    __shared__ float4 skc[RC_BLK];
    __shared__ float2 ses[RC_BLK];
    int b  = blockIdx.y;
    int nA = blockIdx.x * (RC_BLK * 2) + threadIdx.x;
    int nB = nA + RC_BLK;
    int k0 = blockIdx.z * kchunk;
    int k1 = min(k0 + kchunk, NK);

    float xA = 0.f, yA = 0.f, zA = 0.f, xB = 0.f, yB = 0.f, zB = 0.f;
    if (nA < N) {
        const float* cp = coords + ((size_t)b * N + nA) * 3;
        xA = cp[0]; yA = cp[1]; zA = cp[2];
    }
    if (nB < N) {
        const float* cp = coords + ((size_t)b * N + nB) * 3;
        xB = cp[0]; yB = cp[1]; zB = cp[2];
    }
    float accA = 0.f, accB = 0.f;

    for (int t = k0; t < k1; t += RC_BLK) {
        int nt = min(RC_BLK, k1 - t);
        if ((int)threadIdx.x < nt) {
            int k = t + threadIdx.x;
            skc[threadIdx.x] = g_kc4[k];
            ses[threadIdx.x] = g_es[b * NK + k];
        }
        __syncthreads();
        #pragma unroll 4
        for (int j = 0; j < nt; j++) {
            float4 kc = skc[j];
            float2 es = ses[j];
            float thA = fmaf(kc.x, xA, fmaf(kc.y, yA, kc.z * zA));
            float thB = fmaf(kc.x, xB, fmaf(kc.y, yB, kc.z * zB));
            float sA, cA, sB, cB;
            __sincosf(thA, &sA, &cA);
            __sincosf(thB, &sB, &cB);
            accA = fmaf(es.x, cA, accA);
            accA = fmaf(es.y, sA, accA);
            accB = fmaf(es.x, cB, accB);
            accB = fmaf(es.y, sB, accB);
        }
        __syncthreads();
    }
    if (nA < N) atomicAdd(&g_recip[b * N + nA], accA);
    if (nB < N) atomicAdd(&g_recip[b * N + nB], accB);
}

// ---------------- kernel 5: finalize -----------------------------------------
__global__ void fin_kernel(const float* __restrict__ q,
                           const float* __restrict__ volume,
                           const float* __restrict__ bewald,
                           float* __restrict__ out, int BN) {
    int i = blockIdx.x * blockDim.x + threadIdx.x;
    if (i >= BN) return;
    const float BOHR = 1.8897261258369282f;
    const float INV_SQRT_PI = 0.5641895835477563f;
    float scale = BOHR / (CUDART_PI_F * volume[0]);
    float selfc = 2.0f * bewald[0] * BOHR * INV_SQRT_PI;
    float qi = q[i];
    float phi = g_recip[i] * scale - qi * selfc;
    out[i] = 0.5f * qi * phi;
    out[BN + i] = phi;
}

// ---------------------------------------------------------------------------
extern "C" void kernel_launch(void* const* d_in, const int* in_sizes, int n_in,
                              void* d_out, int out_size) {
    const float* coords   = (const float*)d_in[0];
    const float* q        = (const float*)d_in[1];
    const float* cell_inv = (const float*)d_in[2];
    const float* kvec     = (const float*)d_in[3];
    const float* expfac   = (const float*)d_in[4];
    const float* volume   = (const float*)d_in[5];
    const float* bewald   = (const float*)d_in[6];
    float* out = (float*)d_out;

    int BN = in_sizes[1];       // B*N
    int NK = in_sizes[4];
    int B  = 2;                 // fixed shape for this problem
    int N  = BN / B;
    int BK = B * NK;

    kc_kernel<<<(NK + 255) / 256, 256>>>(kvec, cell_inv, NK);

    int zmax = max(BK, BN);
    zero_kernel<<<(zmax + 255) / 256, 256>>>(BK, BN);

    // structure factor: 512 k / block, 64 atom-chunks -> 1024 blocks
    {
        int nchunks = 64;
        int nchunk = (N + nchunks - 1) / nchunks;
        dim3 grid((NK + SF_BLK * 2 - 1) / (SF_BLK * 2), B, nchunks);
        sf_kernel<<<grid, SF_BLK>>>(coords, q, N, NK, nchunk);
    }

    es_kernel<<<(BK + 255) / 256, 256>>>(expfac, NK, BK);

    // recip: 512 atoms / block, 64 k-chunks -> 1024 blocks
    {
        int kchunks = 64;
        int kchunk = (NK + kchunks - 1) / kchunks;
        dim3 grid((N + RC_BLK * 2 - 1) / (RC_BLK * 2), B, kchunks);
        recip_kernel<<<grid, RC_BLK>>>(coords, N, NK, kchunk);
    }

    fin_kernel<<<(BN + 255) / 256, 256>>>(q, volume, bewald, out, BN);
}

// round 3
// speedup vs baseline: 1.1419x; 1.0483x over previous
#include <cuda_runtime.h>
#include <math_constants.h>

// ---------------------------------------------------------------------------
// EwaldReciprocal: B=2, N=4096, NK=4096
// Phase 1 (sf):    S[b,k]     = sum_n q[b,n] * exp(i * kc[k].r[b,n])
// Phase 2 (recip): recip[b,n] = sum_k expfac[k]*(Sre*cos(th) + Sim*sin(th))
// kc computed inline (no kc kernel); expfac folded into recip staging (no es
// kernel). 4 launches total: zero, sf, recip, fin. MUFU-bound inner loops.
// ---------------------------------------------------------------------------

#define MAXBK  32768
#define MAXBN  32768

__device__ float  g_Sre[MAXBK];
__device__ float  g_Sim[MAXBK];
__device__ float  g_recip[MAXBN];

// ---------------- kernel 1: zero accumulators -------------------------------
__global__ void zero_kernel(int BK, int BN) {
    int i = blockIdx.x * blockDim.x + threadIdx.x;
    if (i < BK) { g_Sre[i] = 0.0f; g_Sim[i] = 0.0f; }
    if (i < BN) { g_recip[i] = 0.0f; }
}

// ---------------- kernel 2: structure factor --------------------------------
// 2 k-vectors per thread (block covers 512 k's); grid.z = atom chunks.
// kc = 2*pi * kvec @ cell_inv computed inline per thread.
#define SF_BLK 256
__global__ void sf_kernel(const float* __restrict__ coords,
                          const float* __restrict__ q,
                          const float* __restrict__ kvec,
                          const float* __restrict__ cell_inv,
                          int N, int NK, int nchunk) {
    __shared__ float4 sh[SF_BLK];
    int b  = blockIdx.y;
    int kA = blockIdx.x * (SF_BLK * 2) + threadIdx.x;
    int kB = kA + SF_BLK;
    int n0 = blockIdx.z * nchunk;
    int n1 = min(n0 + nchunk, N);

    const float twopi = 6.283185307179586f;
    float ci[9];
    #pragma unroll
    for (int i = 0; i < 9; i++) ci[i] = __ldg(&cell_inv[i]);

    float4 kcA = make_float4(0.f, 0.f, 0.f, 0.f);
    float4 kcB = make_float4(0.f, 0.f, 0.f, 0.f);
    if (kA < NK) {
        float kx = kvec[kA * 3 + 0], ky = kvec[kA * 3 + 1], kz = kvec[kA * 3 + 2];
        kcA.x = twopi * (kx * ci[0] + ky * ci[3] + kz * ci[6]);
        kcA.y = twopi * (kx * ci[1] + ky * ci[4] + kz * ci[7]);
        kcA.z = twopi * (kx * ci[2] + ky * ci[5] + kz * ci[8]);
    }
    if (kB < NK) {
        float kx = kvec[kB * 3 + 0], ky = kvec[kB * 3 + 1], kz = kvec[kB * 3 + 2];
        kcB.x = twopi * (kx * ci[0] + ky * ci[3] + kz * ci[6]);
        kcB.y = twopi * (kx * ci[1] + ky * ci[4] + kz * ci[7]);
        kcB.z = twopi * (kx * ci[2] + ky * ci[5] + kz * ci[8]);
    }

    float sreA = 0.f, simA = 0.f, sreB = 0.f, simB = 0.f;

    for (int t = n0; t < n1; t += SF_BLK) {
        int nt = min(SF_BLK, n1 - t);
        if ((int)threadIdx.x < nt) {
            int n = t + threadIdx.x;
            const float* cp = coords + ((size_t)b * N + n) * 3;
            sh[threadIdx.x] = make_float4(cp[0], cp[1], cp[2], q[(size_t)b * N + n]);
        }
        __syncthreads();
        #pragma unroll 4
        for (int j = 0; j < nt; j++) {
            float4 a = sh[j];
            float thA = fmaf(kcA.x, a.x, fmaf(kcA.y, a.y, kcA.z * a.z));
            float thB = fmaf(kcB.x, a.x, fmaf(kcB.y, a.y, kcB.z * a.z));
            float sA, cA, sB, cB;
            __sincosf(thA, &sA, &cA);
            __sincosf(thB, &sB, &cB);
            sreA = fmaf(a.w, cA, sreA);
            simA = fmaf(a.w, sA, simA);
            sreB = fmaf(a.w, cB, sreB);
            simB = fmaf(a.w, sB, simB);
        }
        __syncthreads();
    }
    if (kA < NK) {
        atomicAdd(&g_Sre[b * NK + kA], sreA);
        atomicAdd(&g_Sim[b * NK + kA], simA);
    }
    if (kB < NK) {
        atomicAdd(&g_Sre[b * NK + kB], sreB);
        atomicAdd(&g_Sim[b * NK + kB], simB);
    }
}

// ---------------- kernel 3: reciprocal-space potential per atom -------------
// 2 atoms per thread (block covers 512 atoms); grid.z = k chunks.
// Staging computes kc inline and folds expfac into (Sre, Sim).
#define RC_BLK 256
__global__ void recip_kernel(const float* __restrict__ coords,
                             const float* __restrict__ expfac,
                             const float* __restrict__ kvec,
                             const float* __restrict__ cell_inv,
                             int N, int NK, int kchunk) {
    __shared__ float4 skc[RC_BLK];
    __shared__ float2 ses[RC_BLK];
    int b  = blockIdx.y;
    int nA = blockIdx.x * (RC_BLK * 2) + threadIdx.x;
    int nB = nA + RC_BLK;
    int k0 = blockIdx.z * kchunk;
    int k1 = min(k0 + kchunk, NK);

    const float twopi = 6.283185307179586f;
    float ci[9];
    #pragma unroll
    for (int i = 0; i < 9; i++) ci[i] = __ldg(&cell_inv[i]);

    float xA = 0.f, yA = 0.f, zA = 0.f, xB = 0.f, yB = 0.f, zB = 0.f;
    if (nA < N) {
        const float* cp = coords + ((size_t)b * N + nA) * 3;
        xA = cp[0]; yA = cp[1]; zA = cp[2];
    }
    if (nB < N) {
        const float* cp = coords + ((size_t)b * N + nB) * 3;
        xB = cp[0]; yB = cp[1]; zB = cp[2];
    }
    float accA = 0.f, accB = 0.f;

    for (int t = k0; t < k1; t += RC_BLK) {
        int nt = min(RC_BLK, k1 - t);
        if ((int)threadIdx.x < nt) {
            int k = t + threadIdx.x;
            float kx = kvec[k * 3 + 0], ky = kvec[k * 3 + 1], kz = kvec[k * 3 + 2];
            float4 kc;
            kc.x = twopi * (kx * ci[0] + ky * ci[3] + kz * ci[6]);
            kc.y = twopi * (kx * ci[1] + ky * ci[4] + kz * ci[7]);
            kc.z = twopi * (kx * ci[2] + ky * ci[5] + kz * ci[8]);
            kc.w = 0.f;
            skc[threadIdx.x] = kc;
            float e = expfac[k];
            ses[threadIdx.x] = make_float2(e * g_Sre[b * NK + k],
                                           e * g_Sim[b * NK + k]);
        }
        __syncthreads();
        #pragma unroll 4
        for (int j = 0; j < nt; j++) {
            float4 kc = skc[j];
            float2 es = ses[j];
            float thA = fmaf(kc.x, xA, fmaf(kc.y, yA, kc.z * zA));
            float thB = fmaf(kc.x, xB, fmaf(kc.y, yB, kc.z * zB));
            float sA, cA, sB, cB;
            __sincosf(thA, &sA, &cA);
            __sincosf(thB, &sB, &cB);
            accA = fmaf(es.x, cA, accA);
            accA = fmaf(es.y, sA, accA);
            accB = fmaf(es.x, cB, accB);
            accB = fmaf(es.y, sB, accB);
        }
        __syncthreads();
    }
    if (nA < N) atomicAdd(&g_recip[b * N + nA], accA);
    if (nB < N) atomicAdd(&g_recip[b * N + nB], accB);
}

// ---------------- kernel 4: finalize -----------------------------------------
__global__ void fin_kernel(const float* __restrict__ q,
                           const float* __restrict__ volume,
                           const float* __restrict__ bewald,
                           float* __restrict__ out, int BN) {
    int i = blockIdx.x * blockDim.x + threadIdx.x;
    if (i >= BN) return;
    const float BOHR = 1.8897261258369282f;
    const float INV_SQRT_PI = 0.5641895835477563f;
    float scale = BOHR / (CUDART_PI_F * volume[0]);
    float selfc = 2.0f * bewald[0] * BOHR * INV_SQRT_PI;
    float qi = q[i];
    float phi = g_recip[i] * scale - qi * selfc;
    out[i] = 0.5f * qi * phi;
    out[BN + i] = phi;
}

// ---------------------------------------------------------------------------
extern "C" void kernel_launch(void* const* d_in, const int* in_sizes, int n_in,
                              void* d_out, int out_size) {
    const float* coords   = (const float*)d_in[0];
    const float* q        = (const float*)d_in[1];
    const float* cell_inv = (const float*)d_in[2];
    const float* kvec     = (const float*)d_in[3];
    const float* expfac   = (const float*)d_in[4];
    const float* volume   = (const float*)d_in[5];
    const float* bewald   = (const float*)d_in[6];
    float* out = (float*)d_out;

    int BN = in_sizes[1];       // B*N
    int NK = in_sizes[4];
    int B  = 2;                 // fixed shape for this problem
    int N  = BN / B;
    int BK = B * NK;

    int zmax = max(BK, BN);
    zero_kernel<<<(zmax + 255) / 256, 256>>>(BK, BN);

    // structure factor: 512 k / block, 64 atom-chunks -> 1024 blocks
    {
        int nchunks = 64;
        int nchunk = (N + nchunks - 1) / nchunks;
        dim3 grid((NK + SF_BLK * 2 - 1) / (SF_BLK * 2), B, nchunks);
        sf_kernel<<<grid, SF_BLK>>>(coords, q, kvec, cell_inv, N, NK, nchunk);
    }

    // recip: 512 atoms / block, 64 k-chunks -> 1024 blocks
    {
        int kchunks = 64;
        int kchunk = (NK + kchunks - 1) / kchunks;
        dim3 grid((N + RC_BLK * 2 - 1) / (RC_BLK * 2), B, kchunks);
        recip_kernel<<<grid, RC_BLK>>>(coords, expfac, kvec, cell_inv,
                                       N, NK, kchunk);
    }

    fin_kernel<<<(BN + 255) / 256, 256>>>(q, volume, bewald, out, BN);
}

// round 4
// speedup vs baseline: 1.1489x; 1.0062x over previous
#include <cuda_runtime.h>
#include <math_constants.h>

// ---------------------------------------------------------------------------
// EwaldReciprocal: B=2, N=4096, NK=4096 — 2-launch version.
//   sf:    S_part[z][b][k] = sum_{n in chunk z} q * exp(i * kc[k].r[b,n])
//   recip: recip[b,n] = sum_k expfac[k]*(Sre*cos+Sim*sin); last z-block per
//          (x,y) slice finalizes phi and resets accumulators (graph-replay
//          safe: all device state returns to zero after every call).
// ---------------------------------------------------------------------------

#define NCH_SF 32                 // sf atom-chunks (= partial depth)
#define MAXK   8192
#define MAXBN  32768

__device__ float2 g_Spart[NCH_SF * 2 * MAXK];  // [z][b][k]
__device__ float  g_recip[MAXBN];              // zero at entry, re-zeroed by fin
__device__ int    g_cnt[64];                   // per (x,y) slice arrival counter

// ---------------- kernel 1: structure factor partials -----------------------
// 1 k per thread; grid: (NK/256, B, NCH_SF). kc inline. No atomics, no zeroing.
#define SF_BLK 256
__global__ void sf_kernel(const float* __restrict__ coords,
                          const float* __restrict__ q,
                          const float* __restrict__ kvec,
                          const float* __restrict__ cell_inv,
                          int N, int NK, int nchunk) {
    __shared__ float4 sh[SF_BLK];
    int b = blockIdx.y;
    int z = blockIdx.z;
    int k = blockIdx.x * SF_BLK + threadIdx.x;
    int n0 = z * nchunk;
    int n1 = min(n0 + nchunk, N);

    const float twopi = 6.283185307179586f;
    float ci[9];
    #pragma unroll
    for (int i = 0; i < 9; i++) ci[i] = __ldg(&cell_inv[i]);

    float kcx = 0.f, kcy = 0.f, kcz = 0.f;
    if (k < NK) {
        float kx = kvec[k * 3 + 0], ky = kvec[k * 3 + 1], kz = kvec[k * 3 + 2];
        kcx = twopi * (kx * ci[0] + ky * ci[3] + kz * ci[6]);
        kcy = twopi * (kx * ci[1] + ky * ci[4] + kz * ci[7]);
        kcz = twopi * (kx * ci[2] + ky * ci[5] + kz * ci[8]);
    }

    float sre = 0.f, sim = 0.f;

    for (int t = n0; t < n1; t += SF_BLK) {
        int nt = min(SF_BLK, n1 - t);
        if ((int)threadIdx.x < nt) {
            int n = t + threadIdx.x;
            const float* cp = coords + ((size_t)b * N + n) * 3;
            sh[threadIdx.x] = make_float4(cp[0], cp[1], cp[2], q[(size_t)b * N + n]);
        }
        __syncthreads();
        #pragma unroll 4
        for (int j = 0; j < nt; j++) {
            float4 a = sh[j];
            float th = fmaf(kcx, a.x, fmaf(kcy, a.y, kcz * a.z));
            float s, c;
            __sincosf(th, &s, &c);
            sre = fmaf(a.w, c, sre);
            sim = fmaf(a.w, s, sim);
        }
        __syncthreads();
    }
    if (k < NK)
        g_Spart[(z * 2 + b) * NK + k] = make_float2(sre, sim);
}

// ---------------- kernel 2: recip + fused finalize ---------------------------
// 2 atoms per thread; grid: (N/512, B, 64). Staging sums the 32 S-partials and
// folds expfac; kc inline. Last z-block per (x,y) finalizes & resets state.
#define RC_BLK 256
__global__ void recip_kernel(const float* __restrict__ coords,
                             const float* __restrict__ q,
                             const float* __restrict__ expfac,
                             const float* __restrict__ kvec,
                             const float* __restrict__ cell_inv,
                             const float* __restrict__ volume,
                             const float* __restrict__ bewald,
                             float* __restrict__ out,
                             int N, int NK, int kchunk, int BN) {
    __shared__ float4 skc[RC_BLK];
    __shared__ float2 ses[RC_BLK];
    __shared__ int s_last;
    int b  = blockIdx.y;
    int nA = blockIdx.x * (RC_BLK * 2) + threadIdx.x;
    int nB = nA + RC_BLK;
    int k0 = blockIdx.z * kchunk;
    int k1 = min(k0 + kchunk, NK);

    const float twopi = 6.283185307179586f;
    float ci[9];
    #pragma unroll
    for (int i = 0; i < 9; i++) ci[i] = __ldg(&cell_inv[i]);

    float xA = 0.f, yA = 0.f, zA = 0.f, xB = 0.f, yB = 0.f, zB = 0.f;
    if (nA < N) {
        const float* cp = coords + ((size_t)b * N + nA) * 3;
        xA = cp[0]; yA = cp[1]; zA = cp[2];
    }
    if (nB < N) {
        const float* cp = coords + ((size_t)b * N + nB) * 3;
        xB = cp[0]; yB = cp[1]; zB = cp[2];
    }
    float accA = 0.f, accB = 0.f;

    for (int t = k0; t < k1; t += RC_BLK) {
        int nt = min(RC_BLK, k1 - t);
        if ((int)threadIdx.x < nt) {
            int k = t + threadIdx.x;
            float kx = kvec[k * 3 + 0], ky = kvec[k * 3 + 1], kz = kvec[k * 3 + 2];
            float4 kc;
            kc.x = twopi * (kx * ci[0] + ky * ci[3] + kz * ci[6]);
            kc.y = twopi * (kx * ci[1] + ky * ci[4] + kz * ci[7]);
            kc.z = twopi * (kx * ci[2] + ky * ci[5] + kz * ci[8]);
            kc.w = 0.f;
            skc[threadIdx.x] = kc;
            // sum the 32 structure-factor partials, fold expfac
            float sre = 0.f, sim = 0.f;
            #pragma unroll
            for (int zz = 0; zz < NCH_SF; zz++) {
                float2 p = g_Spart[(zz * 2 + b) * NK + k];
                sre += p.x; sim += p.y;
            }
            float e = expfac[k];
            ses[threadIdx.x] = make_float2(e * sre, e * sim);
        }
        __syncthreads();
        #pragma unroll 4
        for (int j = 0; j < nt; j++) {
            float4 kc = skc[j];
            float2 es = ses[j];
            float thA = fmaf(kc.x, xA, fmaf(kc.y, yA, kc.z * zA));
            float thB = fmaf(kc.x, xB, fmaf(kc.y, yB, kc.z * zB));
            float sA, cA, sB, cB;
            __sincosf(thA, &sA, &cA);
            __sincosf(thB, &sB, &cB);
            accA = fmaf(es.x, cA, accA);
            accA = fmaf(es.y, sA, accA);
            accB = fmaf(es.x, cB, accB);
            accB = fmaf(es.y, sB, accB);
        }
        __syncthreads();
    }
    if (nA < N) atomicAdd(&g_recip[b * N + nA], accA);
    if (nB < N) atomicAdd(&g_recip[b * N + nB], accB);

    // ---- arrival counter: last z-block of this (x,y) slice finalizes -------
    __threadfence();
    int slice = blockIdx.y * gridDim.x + blockIdx.x;
    if (threadIdx.x == 0) {
        int c = atomicAdd(&g_cnt[slice], 1);
        s_last = (c == (int)gridDim.z - 1) ? 1 : 0;
    }
    __syncthreads();
    if (s_last) {
        const float BOHR = 1.8897261258369282f;
        const float INV_SQRT_PI = 0.5641895835477563f;
        float scale = BOHR / (CUDART_PI_F * volume[0]);
        float selfc = 2.0f * bewald[0] * BOHR * INV_SQRT_PI;
        int base = blockIdx.x * (RC_BLK * 2);
        #pragma unroll
        for (int a = 0; a < 2; a++) {
            int n = base + a * RC_BLK + threadIdx.x;
            if (n < N) {
                int i = b * N + n;
                float r = g_recip[i];
                g_recip[i] = 0.0f;                 // reset for next replay
                float qi = q[i];
                float phi = r * scale - qi * selfc;
                out[i] = 0.5f * qi * phi;
                out[BN + i] = phi;
            }
        }
        if (threadIdx.x == 0) g_cnt[slice] = 0;    // reset counter
    }
}

// ---------------------------------------------------------------------------
extern "C" void kernel_launch(void* const* d_in, const int* in_sizes, int n_in,
                              void* d_out, int out_size) {
    const float* coords   = (const float*)d_in[0];
    const float* q        = (const float*)d_in[1];
    const float* cell_inv = (const float*)d_in[2];
    const float* kvec     = (const float*)d_in[3];
    const float* expfac   = (const float*)d_in[4];
    const float* volume   = (const float*)d_in[5];
    const float* bewald   = (const float*)d_in[6];
    float* out = (float*)d_out;

    int BN = in_sizes[1];       // B*N
    int NK = in_sizes[4];
    int B  = 2;                 // fixed shape for this problem
    int N  = BN / B;

    // sf: 256 k / block, NCH_SF atom-chunks -> 16*2*32 = 1024 blocks
    {
        int nchunk = (N + NCH_SF - 1) / NCH_SF;
        dim3 grid((NK + SF_BLK - 1) / SF_BLK, B, NCH_SF);
        sf_kernel<<<grid, SF_BLK>>>(coords, q, kvec, cell_inv, N, NK, nchunk);
    }

    // recip (+fused fin): 512 atoms / block, 64 k-chunks -> 8*2*64 = 1024 blocks
    {
        int kchunks = 64;
        int kchunk = (NK + kchunks - 1) / kchunks;
        dim3 grid((N + RC_BLK * 2 - 1) / (RC_BLK * 2), B, kchunks);
        recip_kernel<<<grid, RC_BLK>>>(coords, q, expfac, kvec, cell_inv,
                                       volume, bewald, out, N, NK, kchunk, BN);
    }
}